// round 11
// baseline (speedup 1.0000x reference)
#include <cuda_runtime.h>
#include <math.h>

#define NN 10000
#define NV 2500            // NN/4
#define OUTF 64
#define SMAX 10016
#define NSORT 10048
#define NBUCK 4096
#define JPSB 40            // blocks in k_jps (all co-resident -> grid barrier safe)
#define RPB 250            // rows per jps block

// ---- static scratch ----
__device__ float    g_Wh[NN * OUTF];
__device__ float    g_esrc[NN];
__device__ int      g_Emax;
__device__ unsigned g_bar;            // jps grid-barrier counter (self-resetting)
__device__ float2   g_pb2[NN];        // {bp, bn} (scan layout)
__device__ float4   g_jt4[NN];        // {bp, bn, hT, 0} (SpMM layout)
__device__ unsigned g_nib4[(size_t)(NN / 4) * NV];
__device__ float2   g_rw[NN];         // {py=1/S', pz=rho/S'}
__device__ int      g_sj[(size_t)NN * SMAX];
__device__ int      g_histU[NBUCK], g_histV[NBUCK];
__device__ int      g_offU[NBUCK + 1], g_offV[NBUCK + 1];
__device__ int      g_curU[NBUCK], g_curV[NBUCK];
__device__ float2   g_sU2[NSORT];     // {u, idx_bits}
__device__ float4   g_sV4[NSORT];     // {v, u, idx_bits, 0}

__device__ __forceinline__ int fkey(float x) {
    int ix = __float_as_int(x);
    return ix >= 0 ? ix : (ix ^ 0x7fffffff);
}
__device__ __forceinline__ float funkey(int k) {
    return __int_as_float(k >= 0 ? k : (k ^ 0x7fffffff));
}
__device__ __forceinline__ unsigned buck(float x) {
    unsigned b = __float_as_uint(x) >> 19;
    return b > (NBUCK - 1u) ? (NBUCK - 1u) : b;
}
// grid barrier: all JPSB blocks resident by construction. fence -> arrive -> spin.
__device__ __forceinline__ void gridbar(unsigned target) {
    __syncthreads();
    if (threadIdx.x == 0) {
        __threadfence();
        atomicAdd(&g_bar, 1u);
        while (*((volatile unsigned*)&g_bar) < target) { }
    }
    __syncthreads();
}

// ---------------------------------------------------------------------------
// K1: Wh = h @ W. 64 rows x 32 cols per block (314 blocks -> minimal tail).
// ---------------------------------------------------------------------------
__global__ void __launch_bounds__(256) k_gemm(const float* __restrict__ h,
                                              const float* __restrict__ W) {
    __shared__ float h_s[64][33];
    __shared__ float W_s[32][32];
    int tid = threadIdx.x;
    int tx = tid & 15, ty = tid >> 4;
    int rowTile = blockIdx.x >> 1;
    int gc0 = (blockIdx.x & 1) * 32;
    int gr0 = rowTile * 64;
    float acc[4][2];
#pragma unroll
    for (int i = 0; i < 4; i++) { acc[i][0] = 0.f; acc[i][1] = 0.f; }

    for (int k0 = 0; k0 < 512; k0 += 32) {
        __syncthreads();
#pragma unroll
        for (int it = 0; it < 2; it++) {
            int idx = it * 256 + tid;
            int row = idx >> 3, q = idx & 7;
            float4 h4 = make_float4(0.f, 0.f, 0.f, 0.f);
            if (gr0 + row < NN)
                h4 = *reinterpret_cast<const float4*>(h + (size_t)(gr0 + row) * 512 + k0 + q * 4);
            h_s[row][q * 4 + 0] = h4.x; h_s[row][q * 4 + 1] = h4.y;
            h_s[row][q * 4 + 2] = h4.z; h_s[row][q * 4 + 3] = h4.w;
        }
        {
            int kk = tid >> 3, c4 = (tid & 7) * 4;
            float4 w4 = *reinterpret_cast<const float4*>(W + (size_t)(k0 + kk) * OUTF + gc0 + c4);
            *reinterpret_cast<float4*>(&W_s[kk][c4]) = w4;
        }
        __syncthreads();
#pragma unroll
        for (int kk = 0; kk < 32; kk++) {
            float2 wv = *reinterpret_cast<const float2*>(&W_s[kk][tx * 2]);
            float hv0 = h_s[ty * 4 + 0][kk];
            float hv1 = h_s[ty * 4 + 1][kk];
            float hv2 = h_s[ty * 4 + 2][kk];
            float hv3 = h_s[ty * 4 + 3][kk];
            acc[0][0] = fmaf(hv0, wv.x, acc[0][0]); acc[0][1] = fmaf(hv0, wv.y, acc[0][1]);
            acc[1][0] = fmaf(hv1, wv.x, acc[1][0]); acc[1][1] = fmaf(hv1, wv.y, acc[1][1]);
            acc[2][0] = fmaf(hv2, wv.x, acc[2][0]); acc[2][1] = fmaf(hv2, wv.y, acc[2][1]);
            acc[3][0] = fmaf(hv3, wv.x, acc[3][0]); acc[3][1] = fmaf(hv3, wv.y, acc[3][1]);
        }
    }
#pragma unroll
    for (int i = 0; i < 4; i++) {
        int row = gr0 + ty * 4 + i;
        if (row < NN) {
            float2 o; o.x = acc[i][0]; o.y = acc[i][1];
            *reinterpret_cast<float2*>(g_Wh + (size_t)row * OUTF + gc0 + tx * 2) = o;
        }
    }
}

// ---------------------------------------------------------------------------
// K2 (fused): edge dots + Emax | jtab + hists | prefix | scatter.
// 40 blocks x 256 thr; all resident -> grid barriers.
// ---------------------------------------------------------------------------
__global__ void __launch_bounds__(256) k_jps(const float* __restrict__ a_src,
                                             const float* __restrict__ a_dst,
                                             const float* __restrict__ hub) {
    __shared__ float  s_ed[RPB];
    __shared__ float2 s_uv[RPB];
    __shared__ int    bmax;
    __shared__ int    wpU[8], wpV[8];
    int b = blockIdx.x, t = threadIdx.x;
    int lane = t & 31, w = t >> 5;
    if (t == 0) bmax = 0x80000000;
    // zero histograms (40*256 = 10240 >= 2*4096)
    for (int i = b * 256 + t; i < 2 * NBUCK; i += JPSB * 256) {
        if (i < NBUCK) g_histU[i] = 0;
        else           g_histV[i - NBUCK] = 0;
    }
    __syncthreads();
    // ---- phase A: edge dots for rows [b*RPB, (b+1)*RPB) ----
    float as0 = a_src[lane], as1 = a_src[lane + 32];
    float ad0 = a_dst[lane], ad1 = a_dst[lane + 32];
    for (int r = w; r < RPB; r += 8) {
        int row = b * RPB + r;
        float w0 = g_Wh[(size_t)row * OUTF + lane];
        float w1 = g_Wh[(size_t)row * OUTF + lane + 32];
        float s = w0 * as0 + w1 * as1;
        float d = w0 * ad0 + w1 * ad1;
#pragma unroll
        for (int o = 16; o; o >>= 1) {
            s += __shfl_xor_sync(0xffffffffu, s, o);
            d += __shfl_xor_sync(0xffffffffu, d, o);
        }
        if (lane == 0) {
            g_esrc[row] = s;
            s_ed[r] = d;
            atomicMax(&bmax, fkey(d));
        }
    }
    __syncthreads();
    if (t == 0) atomicMax(&g_Emax, bmax);
    gridbar(JPSB);
    // ---- phase B: per-j tables + keys + histogram ----
    float E = funkey(*((volatile int*)&g_Emax));
    if (t < RPB) {
        int i = b * RPB + t;
        float ed = s_ed[t];
        float bp = expf(ed - E);
        float bn = expf(0.2f * (ed - E));
        float hT = hub[i] * 0.01f;
        float2 pb; pb.x = bp; pb.y = bn;
        g_pb2[i] = pb;
        float4 jt; jt.x = bp; jt.y = bn; jt.z = hT; jt.w = 0.f;
        g_jt4[i] = jt;
        float u = fmaxf((hT / bp) * (1.0f - 2e-6f) - 1e-37f, 0.f);
        float v = fmaxf((hT / bn) * (1.0f - 2e-6f) - 1e-37f, 0.f);
        float2 uv; uv.x = u; uv.y = v;
        s_uv[t] = uv;
        atomicAdd(&g_histU[buck(u)], 1);
        atomicAdd(&g_histV[buck(v)], 1);
    }
    gridbar(2 * JPSB);
    // ---- phase C: exclusive prefix (block 0 only) ----
    if (b == 0) {
        int b0 = t * 16;
        int lU[16], lV[16];
        int aU = 0, aV = 0;
#pragma unroll
        for (int q = 0; q < 16; q++) {
            lU[q] = __ldcg(&g_histU[b0 + q]); aU += lU[q];
            lV[q] = __ldcg(&g_histV[b0 + q]); aV += lV[q];
        }
        int sU = aU, sV = aV;
#pragma unroll
        for (int d = 1; d < 32; d <<= 1) {
            int xU = __shfl_up_sync(0xffffffffu, sU, d);
            int xV = __shfl_up_sync(0xffffffffu, sV, d);
            if (lane >= d) { sU += xU; sV += xV; }
        }
        if (lane == 31) { wpU[w] = sU; wpV[w] = sV; }
        __syncthreads();
        if (t == 0) {
            int accU = 0, accV = 0;
#pragma unroll
            for (int k = 0; k < 8; k++) {
                int xU = wpU[k]; wpU[k] = accU; accU += xU;
                int xV = wpV[k]; wpV[k] = accV; accV += xV;
            }
        }
        __syncthreads();
        int baseU = wpU[w] + sU - aU;
        int baseV = wpV[w] + sV - aV;
#pragma unroll
        for (int q = 0; q < 16; q++) {
            g_offU[b0 + q] = baseU; g_curU[b0 + q] = baseU; baseU += lU[q];
            g_offV[b0 + q] = baseV; g_curV[b0 + q] = baseV; baseV += lV[q];
        }
        if (t == 255) { g_offU[NBUCK] = baseU; g_offV[NBUCK] = baseV; }
    }
    gridbar(3 * JPSB);
    // ---- phase D: scatter into bucket-sorted packed arrays ----
    if (t < RPB) {
        int i = b * RPB + t;
        float2 uv = s_uv[t];
        int p1 = atomicAdd(&g_curU[buck(uv.x)], 1);
        float2 e2; e2.x = uv.x; e2.y = __int_as_float(i);
        g_sU2[p1] = e2;
        int p2 = atomicAdd(&g_curV[buck(uv.y)], 1);
        float4 e4; e4.x = uv.y; e4.y = uv.x; e4.z = __int_as_float(i); e4.w = 0.f;
        g_sV4[p2] = e4;
    }
    if (b == 0 && t == 0) g_bar = 0;   // reset counter for next graph replay
}

// ---------------------------------------------------------------------------
// K3: FUSED adj stream: nibble mask + softmax denominator + row params.
// 4 rows per block (2500 blocks).
// ---------------------------------------------------------------------------
__global__ void __launch_bounds__(256) k_scan(const int* __restrict__ adj) {
    __shared__ float srho[4];
    __shared__ float sred[4][8];
    int t = threadIdx.x, warp = t >> 5;
    int b = blockIdx.x;
    int r0 = b * 4;
    if (t < 4) {
        float es = g_esrc[r0 + t];
        float E = funkey(g_Emax);
        srho[t] = expf(-0.8f * (es + E));
    }
    __syncthreads();
    float rho0 = srho[0], rho1 = srho[1], rho2 = srho[2], rho3 = srho[3];
    float S0 = 0.f, S1 = 0.f, S2 = 0.f, S3 = 0.f;

    const int4* adj4 = reinterpret_cast<const int4*>(adj);
    const float4* pb4 = reinterpret_cast<const float4*>(g_pb2);
    unsigned* nr = g_nib4 + (size_t)b * NV;

    for (int v = t; v < NV; v += 256) {
        int4 a0 = __ldcs(&adj4[(size_t)(r0 + 0) * NV + v]);
        int4 a1 = __ldcs(&adj4[(size_t)(r0 + 1) * NV + v]);
        int4 a2 = __ldcs(&adj4[(size_t)(r0 + 2) * NV + v]);
        int4 a3 = __ldcs(&adj4[(size_t)(r0 + 3) * NV + v]);
        float4 p01 = pb4[2 * v];       // {bp0,bn0,bp1,bn1}
        float4 p23 = pb4[2 * v + 1];   // {bp2,bn2,bp3,bn3}

        float q0, q1, q2, q3;
        q0 = fmaxf(p01.x, rho0 * p01.y); q1 = fmaxf(p01.z, rho0 * p01.w);
        q2 = fmaxf(p23.x, rho0 * p23.y); q3 = fmaxf(p23.z, rho0 * p23.w);
        if (a0.x > 0) S0 += q0;
        if (a0.y > 0) S0 += q1;
        if (a0.z > 0) S0 += q2;
        if (a0.w > 0) S0 += q3;
        q0 = fmaxf(p01.x, rho1 * p01.y); q1 = fmaxf(p01.z, rho1 * p01.w);
        q2 = fmaxf(p23.x, rho1 * p23.y); q3 = fmaxf(p23.z, rho1 * p23.w);
        if (a1.x > 0) S1 += q0;
        if (a1.y > 0) S1 += q1;
        if (a1.z > 0) S1 += q2;
        if (a1.w > 0) S1 += q3;
        q0 = fmaxf(p01.x, rho2 * p01.y); q1 = fmaxf(p01.z, rho2 * p01.w);
        q2 = fmaxf(p23.x, rho2 * p23.y); q3 = fmaxf(p23.z, rho2 * p23.w);
        if (a2.x > 0) S2 += q0;
        if (a2.y > 0) S2 += q1;
        if (a2.z > 0) S2 += q2;
        if (a2.w > 0) S2 += q3;
        q0 = fmaxf(p01.x, rho3 * p01.y); q1 = fmaxf(p01.z, rho3 * p01.w);
        q2 = fmaxf(p23.x, rho3 * p23.y); q3 = fmaxf(p23.z, rho3 * p23.w);
        if (a3.x > 0) S3 += q0;
        if (a3.y > 0) S3 += q1;
        if (a3.z > 0) S3 += q2;
        if (a3.w > 0) S3 += q3;

        unsigned n0 = (unsigned)(a0.x | (a0.y << 1) | (a0.z << 2) | (a0.w << 3));
        unsigned n1 = (unsigned)(a1.x | (a1.y << 1) | (a1.z << 2) | (a1.w << 3));
        unsigned n2 = (unsigned)(a2.x | (a2.y << 1) | (a2.z << 2) | (a2.w << 3));
        unsigned n3 = (unsigned)(a3.x | (a3.y << 1) | (a3.z << 2) | (a3.w << 3));
        nr[v] = n0 | (n1 << 8) | (n2 << 16) | (n3 << 24);
    }
    float S[4] = {S0, S1, S2, S3};
#pragma unroll
    for (int r = 0; r < 4; r++) {
        float s = S[r];
#pragma unroll
        for (int o = 16; o; o >>= 1) s += __shfl_xor_sync(0xffffffffu, s, o);
        if ((t & 31) == 0) sred[r][warp] = s;
    }
    __syncthreads();
    if (t < 4) {
        float s = sred[t][0];
#pragma unroll
        for (int w = 1; w < 8; w++) s += sred[t][w];
        float inv = 1.0f / s;
        float2 rw; rw.x = inv; rw.y = srho[t] * inv;
        g_rw[r0 + t] = rw;
    }
}

// ---------------------------------------------------------------------------
// K4: sorted-prefix prune (packed lists) + sparse SpMM (x4) + ELU. Warp/row.
// ---------------------------------------------------------------------------
__global__ void __launch_bounds__(256) k_pruneout(float* __restrict__ out) {
    int t = threadIdx.x;
    int lane = t & 31, w = t >> 5;
    int row = blockIdx.x * 8 + w;
    float2 rw = g_rw[row];
    float py = rw.x, pz = rw.y;
    const unsigned* nib = g_nib4 + (size_t)(row >> 2) * NV;
    int shift = (row & 3) * 8;
    size_t base = (size_t)row * SMAX;
    int cnt = 0;

    int stopU = g_offU[buck(py) + 1];
    for (int k0 = 0; k0 < stopU; k0 += 32) {
        int k = k0 + lane;
        float2 su = g_sU2[k];
        bool cand = (k < stopU) && (su.x < py);
        int j = 0; bool sv = false;
        if (cand) {
            j = __float_as_int(su.y);
            sv = (nib[j >> 2] >> (shift + (j & 3))) & 1u;
        }
        unsigned sb = __ballot_sync(0xffffffffu, sv);
        if (sv) g_sj[base + cnt + __popc(sb & ((1u << lane) - 1u))] = j;
        cnt += __popc(sb);
    }
    int stopV = g_offV[buck(pz) + 1];
    for (int k0 = 0; k0 < stopV; k0 += 32) {
        int k = k0 + lane;
        float4 sv4 = g_sV4[k];
        bool cand = (k < stopV) && (sv4.x < pz) && !(sv4.y < py);
        int j = 0; bool sv = false;
        if (cand) {
            j = __float_as_int(sv4.z);
            sv = (nib[j >> 2] >> (shift + (j & 3))) & 1u;
        }
        unsigned sb = __ballot_sync(0xffffffffu, sv);
        if (sv) g_sj[base + cnt + __popc(sb & ((1u << lane) - 1u))] = j;
        cnt += __popc(sb);
    }

    // ---- SpMM: 4-deep gather pipeline ----
    int n = cnt;
    const int* sj = g_sj + base;
    const float2* whb = reinterpret_cast<const float2*>(g_Wh);
    float ax = 0.f, ay = 0.f, bx = 0.f, by = 0.f;
    int p = 0;
    for (; p + 3 < n; p += 4) {
        int j0 = sj[p], j1 = sj[p + 1], j2 = sj[p + 2], j3 = sj[p + 3];
        float4 t0 = g_jt4[j0], t1 = g_jt4[j1], t2 = g_jt4[j2], t3 = g_jt4[j3];
        float2 a0 = whb[(size_t)j0 * 32 + lane];
        float2 a1 = whb[(size_t)j1 * 32 + lane];
        float2 a2 = whb[(size_t)j2 * 32 + lane];
        float2 a3 = whb[(size_t)j3 * 32 + lane];
        float w0 = fmaxf(fmaxf(py * t0.x, pz * t0.y) - t0.z, 0.f);
        float w1 = fmaxf(fmaxf(py * t1.x, pz * t1.y) - t1.z, 0.f);
        float w2 = fmaxf(fmaxf(py * t2.x, pz * t2.y) - t2.z, 0.f);
        float w3 = fmaxf(fmaxf(py * t3.x, pz * t3.y) - t3.z, 0.f);
        ax = fmaf(w0, a0.x, ax); ay = fmaf(w0, a0.y, ay);
        bx = fmaf(w1, a1.x, bx); by = fmaf(w1, a1.y, by);
        ax = fmaf(w2, a2.x, ax); ay = fmaf(w2, a2.y, ay);
        bx = fmaf(w3, a3.x, bx); by = fmaf(w3, a3.y, by);
    }
    for (; p < n; p++) {
        int j0 = sj[p];
        float4 t0 = g_jt4[j0];
        float2 a0 = whb[(size_t)j0 * 32 + lane];
        float w0 = fmaxf(fmaxf(py * t0.x, pz * t0.y) - t0.z, 0.f);
        ax = fmaf(w0, a0.x, ax); ay = fmaf(w0, a0.y, ay);
    }
    ax += bx; ay += by;
    float2 o;
    o.x = ax > 0.f ? ax : expm1f(ax);
    o.y = ay > 0.f ? ay : expm1f(ay);
    reinterpret_cast<float2*>(out)[(size_t)row * 32 + lane] = o;
}

// ---------------------------------------------------------------------------
extern "C" void kernel_launch(void* const* d_in, const int* in_sizes, int n_in,
                              void* d_out, int out_size) {
    const float* h = nullptr; const float* W = nullptr;
    const float* a_src = nullptr; const float* a_dst = nullptr;
    const float* hub = nullptr; const int* adj = nullptr;
    int a_count = 0;
    for (int i = 0; i < n_in; i++) {
        int s = in_sizes[i];
        if (s == NN * 512)        h = (const float*)d_in[i];
        else if (s == 512 * OUTF) W = (const float*)d_in[i];
        else if (s == OUTF) { if (a_count++ == 0) a_src = (const float*)d_in[i];
                              else                a_dst = (const float*)d_in[i]; }
        else if (s == NN)         hub = (const float*)d_in[i];
        else if (s == NN * NN)    adj = (const int*)d_in[i];
    }

    void* emax_ptr = nullptr;
    cudaGetSymbolAddress(&emax_ptr, g_Emax);
    cudaMemsetAsync(emax_ptr, 0x80, sizeof(int));

    k_gemm<<<314, 256>>>(h, W);
    k_jps<<<JPSB, 256>>>(a_src, a_dst, hub);
    k_scan<<<2500, 256>>>(adj);
    k_pruneout<<<1250, 256>>>((float*)d_out);
}

// round 12
// speedup vs baseline: 1.1500x; 1.1500x over previous
#include <cuda_runtime.h>
#include <math.h>

#define NN 10000
#define NV 2500            // NN/4
#define OUTF 64
#define SMAX 10016
#define NSORT 10048
#define NBUCK 4096

// ---- static scratch ----
__device__ float    g_Wh[NN * OUTF];
__device__ float    g_esrc[NN];
__device__ float    g_ed[NN];
__device__ int      g_Emax;
__device__ float2   g_pb2[NN];        // {bp, bn} (scan layout)
__device__ float4   g_jt4[NN];        // {bp, bn, hT, 0} (SpMM layout)
__device__ unsigned g_nib4[(size_t)(NN / 4) * NV];
__device__ float2   g_rw[NN];         // {py=1/S', pz=rho/S'}
__device__ int      g_sj[(size_t)NN * SMAX];
__device__ float    g_u[NN];
__device__ float2   g_vu[NN];
__device__ int      g_histU[NBUCK], g_histV[NBUCK];
__device__ int      g_offU[NBUCK + 1], g_offV[NBUCK + 1];
__device__ int      g_curU[NBUCK], g_curV[NBUCK];
__device__ float2   g_sU2[NSORT];     // {u, idx_bits}
__device__ float4   g_sV4[NSORT];     // {v, u, idx_bits, 0}

__device__ __forceinline__ int fkey(float x) {
    int ix = __float_as_int(x);
    return ix >= 0 ? ix : (ix ^ 0x7fffffff);
}
__device__ __forceinline__ float funkey(int k) {
    return __int_as_float(k >= 0 ? k : (k ^ 0x7fffffff));
}
__device__ __forceinline__ unsigned buck(float x) {
    unsigned b = __float_as_uint(x) >> 19;
    return b > (NBUCK - 1u) ? (NBUCK - 1u) : b;
}

// ---------------------------------------------------------------------------
// K1: Wh = h @ W. 64 rows x 32 cols per block (314 blocks -> minimal tail).
// ---------------------------------------------------------------------------
__global__ void __launch_bounds__(256) k_gemm(const float* __restrict__ h,
                                              const float* __restrict__ W) {
    __shared__ float h_s[64][33];
    __shared__ float W_s[32][32];
    int tid = threadIdx.x;
    int tx = tid & 15, ty = tid >> 4;
    int rowTile = blockIdx.x >> 1;
    int gc0 = (blockIdx.x & 1) * 32;
    int gr0 = rowTile * 64;
    float acc[4][2];
#pragma unroll
    for (int i = 0; i < 4; i++) { acc[i][0] = 0.f; acc[i][1] = 0.f; }

    for (int k0 = 0; k0 < 512; k0 += 32) {
        __syncthreads();
#pragma unroll
        for (int it = 0; it < 2; it++) {
            int idx = it * 256 + tid;
            int row = idx >> 3, q = idx & 7;
            float4 h4 = make_float4(0.f, 0.f, 0.f, 0.f);
            if (gr0 + row < NN)
                h4 = *reinterpret_cast<const float4*>(h + (size_t)(gr0 + row) * 512 + k0 + q * 4);
            h_s[row][q * 4 + 0] = h4.x; h_s[row][q * 4 + 1] = h4.y;
            h_s[row][q * 4 + 2] = h4.z; h_s[row][q * 4 + 3] = h4.w;
        }
        {
            int kk = tid >> 3, c4 = (tid & 7) * 4;
            float4 w4 = *reinterpret_cast<const float4*>(W + (size_t)(k0 + kk) * OUTF + gc0 + c4);
            *reinterpret_cast<float4*>(&W_s[kk][c4]) = w4;
        }
        __syncthreads();
#pragma unroll
        for (int kk = 0; kk < 32; kk++) {
            float2 wv = *reinterpret_cast<const float2*>(&W_s[kk][tx * 2]);
            float hv0 = h_s[ty * 4 + 0][kk];
            float hv1 = h_s[ty * 4 + 1][kk];
            float hv2 = h_s[ty * 4 + 2][kk];
            float hv3 = h_s[ty * 4 + 3][kk];
            acc[0][0] = fmaf(hv0, wv.x, acc[0][0]); acc[0][1] = fmaf(hv0, wv.y, acc[0][1]);
            acc[1][0] = fmaf(hv1, wv.x, acc[1][0]); acc[1][1] = fmaf(hv1, wv.y, acc[1][1]);
            acc[2][0] = fmaf(hv2, wv.x, acc[2][0]); acc[2][1] = fmaf(hv2, wv.y, acc[2][1]);
            acc[3][0] = fmaf(hv3, wv.x, acc[3][0]); acc[3][1] = fmaf(hv3, wv.y, acc[3][1]);
        }
    }
#pragma unroll
    for (int i = 0; i < 4; i++) {
        int row = gr0 + ty * 4 + i;
        if (row < NN) {
            float2 o; o.x = acc[i][0]; o.y = acc[i][1];
            *reinterpret_cast<float2*>(g_Wh + (size_t)row * OUTF + gc0 + tx * 2) = o;
        }
    }
}

// ---------------------------------------------------------------------------
// K2: edge dots per row + Emax
// ---------------------------------------------------------------------------
__global__ void k_edot(const float* __restrict__ a_src, const float* __restrict__ a_dst) {
    __shared__ int bmax;
    int t = threadIdx.x;
    if (t == 0) bmax = 0x80000000;
    __syncthreads();
    int lane = t & 31;
    int row = blockIdx.x * 8 + (t >> 5);
    float w0 = g_Wh[(size_t)row * OUTF + lane];
    float w1 = g_Wh[(size_t)row * OUTF + lane + 32];
    float s = w0 * a_src[lane] + w1 * a_src[lane + 32];
    float d = w0 * a_dst[lane] + w1 * a_dst[lane + 32];
#pragma unroll
    for (int o = 16; o; o >>= 1) {
        s += __shfl_xor_sync(0xffffffffu, s, o);
        d += __shfl_xor_sync(0xffffffffu, d, o);
    }
    if (lane == 0) {
        g_esrc[row] = s;
        g_ed[row] = d;
        atomicMax(&bmax, fkey(d));
    }
    __syncthreads();
    if (t == 0) atomicMax(&g_Emax, bmax);
}

// ---------------------------------------------------------------------------
// K3: per-j tables + u/v keys + bucket histograms
// ---------------------------------------------------------------------------
__global__ void k_jtab(const float* __restrict__ hub) {
    int i = blockIdx.x * 256 + threadIdx.x;
    if (i >= NN) return;
    float E = funkey(g_Emax);
    float ed = g_ed[i];
    float bp = expf(ed - E);
    float bn = expf(0.2f * (ed - E));
    float2 pb; pb.x = bp; pb.y = bn;
    g_pb2[i] = pb;
    float hT = hub[i] * 0.01f;
    float4 jt; jt.x = bp; jt.y = bn; jt.z = hT; jt.w = 0.f;
    g_jt4[i] = jt;
    float u = fmaxf((hT / bp) * (1.0f - 2e-6f) - 1e-37f, 0.f);
    float v = fmaxf((hT / bn) * (1.0f - 2e-6f) - 1e-37f, 0.f);
    g_u[i] = u;
    float2 vu; vu.x = v; vu.y = u;
    g_vu[i] = vu;
    atomicAdd(&g_histU[buck(u)], 1);
    atomicAdd(&g_histV[buck(v)], 1);
}

// ---------------------------------------------------------------------------
// K4: exclusive prefix over both histograms — two-level shfl scan
// ---------------------------------------------------------------------------
__global__ void k_pref() {
    __shared__ int wU[32], wV[32];
    int t = threadIdx.x;
    int lane = t & 31, warp = t >> 5;
    int b0 = t * 4;
    int lU[4], lV[4];
    int aU = 0, aV = 0;
#pragma unroll
    for (int q = 0; q < 4; q++) {
        lU[q] = g_histU[b0 + q]; aU += lU[q];
        lV[q] = g_histV[b0 + q]; aV += lV[q];
    }
    int sU = aU, sV = aV;
#pragma unroll
    for (int d = 1; d < 32; d <<= 1) {
        int xU = __shfl_up_sync(0xffffffffu, sU, d);
        int xV = __shfl_up_sync(0xffffffffu, sV, d);
        if (lane >= d) { sU += xU; sV += xV; }
    }
    if (lane == 31) { wU[warp] = sU; wV[warp] = sV; }
    __syncthreads();
    if (warp == 0) {
        int pU = wU[lane], pV = wV[lane];
#pragma unroll
        for (int d = 1; d < 32; d <<= 1) {
            int xU = __shfl_up_sync(0xffffffffu, pU, d);
            int xV = __shfl_up_sync(0xffffffffu, pV, d);
            if (lane >= d) { pU += xU; pV += xV; }
        }
        wU[lane] = pU; wV[lane] = pV;
    }
    __syncthreads();
    int baseU = (warp ? wU[warp - 1] : 0) + sU - aU;
    int baseV = (warp ? wV[warp - 1] : 0) + sV - aV;
#pragma unroll
    for (int q = 0; q < 4; q++) {
        g_offU[b0 + q] = baseU; g_curU[b0 + q] = baseU; baseU += lU[q];
        g_offV[b0 + q] = baseV; g_curV[b0 + q] = baseV; baseV += lV[q];
    }
    if (t == 1023) { g_offU[NBUCK] = baseU; g_offV[NBUCK] = baseV; }
}

// ---------------------------------------------------------------------------
// K5: scatter into bucket-sorted packed arrays
// ---------------------------------------------------------------------------
__global__ void k_scatter() {
    int i = blockIdx.x * 256 + threadIdx.x;
    if (i >= NN) return;
    float u = g_u[i];
    int p1 = atomicAdd(&g_curU[buck(u)], 1);
    float2 e2; e2.x = u; e2.y = __int_as_float(i);
    g_sU2[p1] = e2;
    float2 vu = g_vu[i];
    int p2 = atomicAdd(&g_curV[buck(vu.x)], 1);
    float4 e4; e4.x = vu.x; e4.y = vu.y; e4.z = __int_as_float(i); e4.w = 0.f;
    g_sV4[p2] = e4;
}

// ---------------------------------------------------------------------------
// K6: FUSED adj stream: nibble mask + softmax denominator + row params.
// 4 rows per block (2500 blocks).
// ---------------------------------------------------------------------------
__global__ void __launch_bounds__(256) k_scan(const int* __restrict__ adj) {
    __shared__ float srho[4];
    __shared__ float sred[4][8];
    int t = threadIdx.x, warp = t >> 5;
    int b = blockIdx.x;
    int r0 = b * 4;
    if (t < 4) {
        float es = g_esrc[r0 + t];
        float E = funkey(g_Emax);
        srho[t] = expf(-0.8f * (es + E));
    }
    __syncthreads();
    float rho0 = srho[0], rho1 = srho[1], rho2 = srho[2], rho3 = srho[3];
    float S0 = 0.f, S1 = 0.f, S2 = 0.f, S3 = 0.f;

    const int4* adj4 = reinterpret_cast<const int4*>(adj);
    const float4* pb4 = reinterpret_cast<const float4*>(g_pb2);
    unsigned* nr = g_nib4 + (size_t)b * NV;

    for (int v = t; v < NV; v += 256) {
        int4 a0 = __ldcs(&adj4[(size_t)(r0 + 0) * NV + v]);
        int4 a1 = __ldcs(&adj4[(size_t)(r0 + 1) * NV + v]);
        int4 a2 = __ldcs(&adj4[(size_t)(r0 + 2) * NV + v]);
        int4 a3 = __ldcs(&adj4[(size_t)(r0 + 3) * NV + v]);
        float4 p01 = pb4[2 * v];       // {bp0,bn0,bp1,bn1}
        float4 p23 = pb4[2 * v + 1];   // {bp2,bn2,bp3,bn3}

        float q0, q1, q2, q3;
        q0 = fmaxf(p01.x, rho0 * p01.y); q1 = fmaxf(p01.z, rho0 * p01.w);
        q2 = fmaxf(p23.x, rho0 * p23.y); q3 = fmaxf(p23.z, rho0 * p23.w);
        if (a0.x > 0) S0 += q0;
        if (a0.y > 0) S0 += q1;
        if (a0.z > 0) S0 += q2;
        if (a0.w > 0) S0 += q3;
        q0 = fmaxf(p01.x, rho1 * p01.y); q1 = fmaxf(p01.z, rho1 * p01.w);
        q2 = fmaxf(p23.x, rho1 * p23.y); q3 = fmaxf(p23.z, rho1 * p23.w);
        if (a1.x > 0) S1 += q0;
        if (a1.y > 0) S1 += q1;
        if (a1.z > 0) S1 += q2;
        if (a1.w > 0) S1 += q3;
        q0 = fmaxf(p01.x, rho2 * p01.y); q1 = fmaxf(p01.z, rho2 * p01.w);
        q2 = fmaxf(p23.x, rho2 * p23.y); q3 = fmaxf(p23.z, rho2 * p23.w);
        if (a2.x > 0) S2 += q0;
        if (a2.y > 0) S2 += q1;
        if (a2.z > 0) S2 += q2;
        if (a2.w > 0) S2 += q3;
        q0 = fmaxf(p01.x, rho3 * p01.y); q1 = fmaxf(p01.z, rho3 * p01.w);
        q2 = fmaxf(p23.x, rho3 * p23.y); q3 = fmaxf(p23.z, rho3 * p23.w);
        if (a3.x > 0) S3 += q0;
        if (a3.y > 0) S3 += q1;
        if (a3.z > 0) S3 += q2;
        if (a3.w > 0) S3 += q3;

        unsigned n0 = (unsigned)(a0.x | (a0.y << 1) | (a0.z << 2) | (a0.w << 3));
        unsigned n1 = (unsigned)(a1.x | (a1.y << 1) | (a1.z << 2) | (a1.w << 3));
        unsigned n2 = (unsigned)(a2.x | (a2.y << 1) | (a2.z << 2) | (a2.w << 3));
        unsigned n3 = (unsigned)(a3.x | (a3.y << 1) | (a3.z << 2) | (a3.w << 3));
        nr[v] = n0 | (n1 << 8) | (n2 << 16) | (n3 << 24);
    }
    float S[4] = {S0, S1, S2, S3};
#pragma unroll
    for (int r = 0; r < 4; r++) {
        float s = S[r];
#pragma unroll
        for (int o = 16; o; o >>= 1) s += __shfl_xor_sync(0xffffffffu, s, o);
        if ((t & 31) == 0) sred[r][warp] = s;
    }
    __syncthreads();
    if (t < 4) {
        float s = sred[t][0];
#pragma unroll
        for (int w = 1; w < 8; w++) s += sred[t][w];
        float inv = 1.0f / s;
        float2 rw; rw.x = inv; rw.y = srho[t] * inv;
        g_rw[r0 + t] = rw;
    }
}

// ---------------------------------------------------------------------------
// K7: sorted-prefix prune (packed lists) + sparse SpMM (x4) + ELU. Warp/row.
// ---------------------------------------------------------------------------
__global__ void __launch_bounds__(256) k_pruneout(float* __restrict__ out) {
    int t = threadIdx.x;
    int lane = t & 31, w = t >> 5;
    int row = blockIdx.x * 8 + w;
    float2 rw = g_rw[row];
    float py = rw.x, pz = rw.y;
    const unsigned* nib = g_nib4 + (size_t)(row >> 2) * NV;
    int shift = (row & 3) * 8;
    size_t base = (size_t)row * SMAX;
    int cnt = 0;

    int stopU = g_offU[buck(py) + 1];
    for (int k0 = 0; k0 < stopU; k0 += 32) {
        int k = k0 + lane;
        float2 su = g_sU2[k];
        bool cand = (k < stopU) && (su.x < py);
        int j = 0; bool sv = false;
        if (cand) {
            j = __float_as_int(su.y);
            sv = (nib[j >> 2] >> (shift + (j & 3))) & 1u;
        }
        unsigned sb = __ballot_sync(0xffffffffu, sv);
        if (sv) g_sj[base + cnt + __popc(sb & ((1u << lane) - 1u))] = j;
        cnt += __popc(sb);
    }
    int stopV = g_offV[buck(pz) + 1];
    for (int k0 = 0; k0 < stopV; k0 += 32) {
        int k = k0 + lane;
        float4 sv4 = g_sV4[k];
        bool cand = (k < stopV) && (sv4.x < pz) && !(sv4.y < py);
        int j = 0; bool sv = false;
        if (cand) {
            j = __float_as_int(sv4.z);
            sv = (nib[j >> 2] >> (shift + (j & 3))) & 1u;
        }
        unsigned sb = __ballot_sync(0xffffffffu, sv);
        if (sv) g_sj[base + cnt + __popc(sb & ((1u << lane) - 1u))] = j;
        cnt += __popc(sb);
    }

    // ---- SpMM: 4-deep gather pipeline ----
    int n = cnt;
    const int* sj = g_sj + base;
    const float2* whb = reinterpret_cast<const float2*>(g_Wh);
    float ax = 0.f, ay = 0.f, bx = 0.f, by = 0.f;
    int p = 0;
    for (; p + 3 < n; p += 4) {
        int j0 = sj[p], j1 = sj[p + 1], j2 = sj[p + 2], j3 = sj[p + 3];
        float4 t0 = g_jt4[j0], t1 = g_jt4[j1], t2 = g_jt4[j2], t3 = g_jt4[j3];
        float2 a0 = whb[(size_t)j0 * 32 + lane];
        float2 a1 = whb[(size_t)j1 * 32 + lane];
        float2 a2 = whb[(size_t)j2 * 32 + lane];
        float2 a3 = whb[(size_t)j3 * 32 + lane];
        float w0 = fmaxf(fmaxf(py * t0.x, pz * t0.y) - t0.z, 0.f);
        float w1 = fmaxf(fmaxf(py * t1.x, pz * t1.y) - t1.z, 0.f);
        float w2 = fmaxf(fmaxf(py * t2.x, pz * t2.y) - t2.z, 0.f);
        float w3 = fmaxf(fmaxf(py * t3.x, pz * t3.y) - t3.z, 0.f);
        ax = fmaf(w0, a0.x, ax); ay = fmaf(w0, a0.y, ay);
        bx = fmaf(w1, a1.x, bx); by = fmaf(w1, a1.y, by);
        ax = fmaf(w2, a2.x, ax); ay = fmaf(w2, a2.y, ay);
        bx = fmaf(w3, a3.x, bx); by = fmaf(w3, a3.y, by);
    }
    for (; p < n; p++) {
        int j0 = sj[p];
        float4 t0 = g_jt4[j0];
        float2 a0 = whb[(size_t)j0 * 32 + lane];
        float w0 = fmaxf(fmaxf(py * t0.x, pz * t0.y) - t0.z, 0.f);
        ax = fmaf(w0, a0.x, ax); ay = fmaf(w0, a0.y, ay);
    }
    ax += bx; ay += by;
    float2 o;
    o.x = ax > 0.f ? ax : expm1f(ax);
    o.y = ay > 0.f ? ay : expm1f(ay);
    reinterpret_cast<float2*>(out)[(size_t)row * 32 + lane] = o;
}

// ---------------------------------------------------------------------------
extern "C" void kernel_launch(void* const* d_in, const int* in_sizes, int n_in,
                              void* d_out, int out_size) {
    const float* h = nullptr; const float* W = nullptr;
    const float* a_src = nullptr; const float* a_dst = nullptr;
    const float* hub = nullptr; const int* adj = nullptr;
    int a_count = 0;
    for (int i = 0; i < n_in; i++) {
        int s = in_sizes[i];
        if (s == NN * 512)        h = (const float*)d_in[i];
        else if (s == 512 * OUTF) W = (const float*)d_in[i];
        else if (s == OUTF) { if (a_count++ == 0) a_src = (const float*)d_in[i];
                              else                a_dst = (const float*)d_in[i]; }
        else if (s == NN)         hub = (const float*)d_in[i];
        else if (s == NN * NN)    adj = (const int*)d_in[i];
    }

    static cudaStream_t s2 = nullptr;
    static cudaEvent_t evF = nullptr, evJ = nullptr;
    static int inited = 0;
    if (!inited) {
        inited = 1;
        if (cudaStreamCreateWithFlags(&s2, cudaStreamNonBlocking) != cudaSuccess) s2 = nullptr;
        if (s2) {
            if (cudaEventCreateWithFlags(&evF, cudaEventDisableTiming) != cudaSuccess ||
                cudaEventCreateWithFlags(&evJ, cudaEventDisableTiming) != cudaSuccess)
                s2 = nullptr;
        }
    }

    void* p = nullptr;
    cudaGetSymbolAddress(&p, g_Emax);
    cudaMemsetAsync(p, 0x80, sizeof(int));
    cudaGetSymbolAddress(&p, g_histU);
    cudaMemsetAsync(p, 0, NBUCK * sizeof(int));
    cudaGetSymbolAddress(&p, g_histV);
    cudaMemsetAsync(p, 0, NBUCK * sizeof(int));

    k_gemm<<<314, 256>>>(h, W);
    k_edot<<<1250, 256>>>(a_src, a_dst);
    k_jtab<<<(NN + 255) / 256, 256>>>(hub);

    if (s2) {
        // fork: sort finalize (pref+scatter) runs beside the big adj scan
        cudaEventRecord(evF, 0);
        cudaStreamWaitEvent(s2, evF, 0);
        k_pref<<<1, 1024, 0, s2>>>();
        k_scatter<<<(NN + 255) / 256, 256, 0, s2>>>();
        cudaEventRecord(evJ, s2);
        k_scan<<<2500, 256>>>(adj);
        cudaStreamWaitEvent(0, evJ, 0);
    } else {
        k_pref<<<1, 1024>>>();
        k_scatter<<<(NN + 255) / 256, 256>>>();
        k_scan<<<2500, 256>>>(adj);
    }
    k_pruneout<<<1250, 256>>>((float*)d_out);
}

// round 13
// speedup vs baseline: 1.1786x; 1.0249x over previous
#include <cuda_runtime.h>
#include <math.h>

#define NN 10000
#define NV 2500            // NN/4
#define OUTF 64
#define SMAX 10016
#define NSORT 10048
#define NBUCK 4096

// ---- static scratch ----
__device__ float    g_Wh[NN * OUTF];
__device__ float    g_esrc[NN];
__device__ float2   g_pb2[NN];        // {bp=e^ed, bn=e^{0.2 ed}} (scan layout)
__device__ float4   g_jt4[NN];        // {bp, bn, hT, 0} (SpMM layout)
__device__ unsigned g_nib4[(size_t)(NN / 4) * NV];
__device__ float2   g_rw[NN];         // {py=1/S'', pz=rho'/S''}
__device__ int      g_sj[(size_t)NN * SMAX];
__device__ float    g_u[NN];
__device__ float2   g_vu[NN];
__device__ int      g_histU[NBUCK], g_histV[NBUCK];
__device__ int      g_offU[NBUCK + 1], g_offV[NBUCK + 1];
__device__ int      g_curU[NBUCK], g_curV[NBUCK];
__device__ float2   g_sU2[NSORT];     // {u, idx_bits}
__device__ float4   g_sV4[NSORT];     // {v, u, idx_bits, 0}

__device__ __forceinline__ unsigned buck(float x) {
    unsigned b = __float_as_uint(x) >> 19;
    return b > (NBUCK - 1u) ? (NBUCK - 1u) : b;
}

// ---------------------------------------------------------------------------
// K1: Wh = h @ W. 64 rows x 32 cols per block (314 blocks -> minimal tail).
// ---------------------------------------------------------------------------
__global__ void __launch_bounds__(256) k_gemm(const float* __restrict__ h,
                                              const float* __restrict__ W) {
    __shared__ float h_s[64][33];
    __shared__ float W_s[32][32];
    int tid = threadIdx.x;
    int tx = tid & 15, ty = tid >> 4;
    int rowTile = blockIdx.x >> 1;
    int gc0 = (blockIdx.x & 1) * 32;
    int gr0 = rowTile * 64;
    float acc[4][2];
#pragma unroll
    for (int i = 0; i < 4; i++) { acc[i][0] = 0.f; acc[i][1] = 0.f; }

    for (int k0 = 0; k0 < 512; k0 += 32) {
        __syncthreads();
#pragma unroll
        for (int it = 0; it < 2; it++) {
            int idx = it * 256 + tid;
            int row = idx >> 3, q = idx & 7;
            float4 h4 = make_float4(0.f, 0.f, 0.f, 0.f);
            if (gr0 + row < NN)
                h4 = *reinterpret_cast<const float4*>(h + (size_t)(gr0 + row) * 512 + k0 + q * 4);
            h_s[row][q * 4 + 0] = h4.x; h_s[row][q * 4 + 1] = h4.y;
            h_s[row][q * 4 + 2] = h4.z; h_s[row][q * 4 + 3] = h4.w;
        }
        {
            int kk = tid >> 3, c4 = (tid & 7) * 4;
            float4 w4 = *reinterpret_cast<const float4*>(W + (size_t)(k0 + kk) * OUTF + gc0 + c4);
            *reinterpret_cast<float4*>(&W_s[kk][c4]) = w4;
        }
        __syncthreads();
#pragma unroll
        for (int kk = 0; kk < 32; kk++) {
            float2 wv = *reinterpret_cast<const float2*>(&W_s[kk][tx * 2]);
            float hv0 = h_s[ty * 4 + 0][kk];
            float hv1 = h_s[ty * 4 + 1][kk];
            float hv2 = h_s[ty * 4 + 2][kk];
            float hv3 = h_s[ty * 4 + 3][kk];
            acc[0][0] = fmaf(hv0, wv.x, acc[0][0]); acc[0][1] = fmaf(hv0, wv.y, acc[0][1]);
            acc[1][0] = fmaf(hv1, wv.x, acc[1][0]); acc[1][1] = fmaf(hv1, wv.y, acc[1][1]);
            acc[2][0] = fmaf(hv2, wv.x, acc[2][0]); acc[2][1] = fmaf(hv2, wv.y, acc[2][1]);
            acc[3][0] = fmaf(hv3, wv.x, acc[3][0]); acc[3][1] = fmaf(hv3, wv.y, acc[3][1]);
        }
    }
#pragma unroll
    for (int i = 0; i < 4; i++) {
        int row = gr0 + ty * 4 + i;
        if (row < NN) {
            float2 o; o.x = acc[i][0]; o.y = acc[i][1];
            *reinterpret_cast<float2*>(g_Wh + (size_t)row * OUTF + gc0 + tx * 2) = o;
        }
    }
}

// ---------------------------------------------------------------------------
// K2 (fused): edge dots + per-j tables + sort keys + histograms.
// E-free formulation: bp=e^ed, bn=e^{0.2ed}; rho'=e^{-0.8 es} applied row-side.
// 1250 blocks x 256 thr; warp per row for dots, threads 0..7 for table math.
// ---------------------------------------------------------------------------
__global__ void k_edjt(const float* __restrict__ a_src, const float* __restrict__ a_dst,
                       const float* __restrict__ hub) {
    __shared__ float sed[8];
    int t = threadIdx.x;
    int lane = t & 31, w = t >> 5;
    int row = blockIdx.x * 8 + w;
    float w0 = g_Wh[(size_t)row * OUTF + lane];
    float w1 = g_Wh[(size_t)row * OUTF + lane + 32];
    float s = w0 * a_src[lane] + w1 * a_src[lane + 32];
    float d = w0 * a_dst[lane] + w1 * a_dst[lane + 32];
#pragma unroll
    for (int o = 16; o; o >>= 1) {
        s += __shfl_xor_sync(0xffffffffu, s, o);
        d += __shfl_xor_sync(0xffffffffu, d, o);
    }
    if (lane == 0) {
        g_esrc[row] = s;
        sed[w] = d;
    }
    __syncthreads();
    if (t < 8) {
        int i = blockIdx.x * 8 + t;
        float ed = sed[t];
        float bp = expf(ed);
        float bn = expf(0.2f * ed);
        float2 pb; pb.x = bp; pb.y = bn;
        g_pb2[i] = pb;
        float hT = hub[i] * 0.01f;
        float4 jt; jt.x = bp; jt.y = bn; jt.z = hT; jt.w = 0.f;
        g_jt4[i] = jt;
        float u = fmaxf((hT / bp) * (1.0f - 2e-6f) - 1e-37f, 0.f);
        float v = fmaxf((hT / bn) * (1.0f - 2e-6f) - 1e-37f, 0.f);
        g_u[i] = u;
        float2 vu; vu.x = v; vu.y = u;
        g_vu[i] = vu;
        atomicAdd(&g_histU[buck(u)], 1);
        atomicAdd(&g_histV[buck(v)], 1);
    }
}

// ---------------------------------------------------------------------------
// K3: exclusive prefix over both histograms — two-level shfl scan
// ---------------------------------------------------------------------------
__global__ void k_pref() {
    __shared__ int wU[32], wV[32];
    int t = threadIdx.x;
    int lane = t & 31, warp = t >> 5;
    int b0 = t * 4;
    int lU[4], lV[4];
    int aU = 0, aV = 0;
#pragma unroll
    for (int q = 0; q < 4; q++) {
        lU[q] = g_histU[b0 + q]; aU += lU[q];
        lV[q] = g_histV[b0 + q]; aV += lV[q];
    }
    int sU = aU, sV = aV;
#pragma unroll
    for (int d = 1; d < 32; d <<= 1) {
        int xU = __shfl_up_sync(0xffffffffu, sU, d);
        int xV = __shfl_up_sync(0xffffffffu, sV, d);
        if (lane >= d) { sU += xU; sV += xV; }
    }
    if (lane == 31) { wU[warp] = sU; wV[warp] = sV; }
    __syncthreads();
    if (warp == 0) {
        int pU = wU[lane], pV = wV[lane];
#pragma unroll
        for (int d = 1; d < 32; d <<= 1) {
            int xU = __shfl_up_sync(0xffffffffu, pU, d);
            int xV = __shfl_up_sync(0xffffffffu, pV, d);
            if (lane >= d) { pU += xU; pV += xV; }
        }
        wU[lane] = pU; wV[lane] = pV;
    }
    __syncthreads();
    int baseU = (warp ? wU[warp - 1] : 0) + sU - aU;
    int baseV = (warp ? wV[warp - 1] : 0) + sV - aV;
#pragma unroll
    for (int q = 0; q < 4; q++) {
        g_offU[b0 + q] = baseU; g_curU[b0 + q] = baseU; baseU += lU[q];
        g_offV[b0 + q] = baseV; g_curV[b0 + q] = baseV; baseV += lV[q];
    }
    if (t == 1023) { g_offU[NBUCK] = baseU; g_offV[NBUCK] = baseV; }
}

// ---------------------------------------------------------------------------
// K4: scatter into bucket-sorted packed arrays
// ---------------------------------------------------------------------------
__global__ void k_scatter() {
    int i = blockIdx.x * 256 + threadIdx.x;
    if (i >= NN) return;
    float u = g_u[i];
    int p1 = atomicAdd(&g_curU[buck(u)], 1);
    float2 e2; e2.x = u; e2.y = __int_as_float(i);
    g_sU2[p1] = e2;
    float2 vu = g_vu[i];
    int p2 = atomicAdd(&g_curV[buck(vu.x)], 1);
    float4 e4; e4.x = vu.x; e4.y = vu.y; e4.z = __int_as_float(i); e4.w = 0.f;
    g_sV4[p2] = e4;
}

// ---------------------------------------------------------------------------
// K5: FUSED adj stream: nibble mask + softmax denominator + row params.
// 4 rows per block (2500 blocks). rho' = exp(-0.8 es) (E-free).
// ---------------------------------------------------------------------------
__global__ void __launch_bounds__(256) k_scan(const int* __restrict__ adj) {
    __shared__ float srho[4];
    __shared__ float sred[4][8];
    int t = threadIdx.x, warp = t >> 5;
    int b = blockIdx.x;
    int r0 = b * 4;
    if (t < 4) {
        float es = g_esrc[r0 + t];
        srho[t] = expf(-0.8f * es);
    }
    __syncthreads();
    float rho0 = srho[0], rho1 = srho[1], rho2 = srho[2], rho3 = srho[3];
    float S0 = 0.f, S1 = 0.f, S2 = 0.f, S3 = 0.f;

    const int4* adj4 = reinterpret_cast<const int4*>(adj);
    const float4* pb4 = reinterpret_cast<const float4*>(g_pb2);
    unsigned* nr = g_nib4 + (size_t)b * NV;

    for (int v = t; v < NV; v += 256) {
        int4 a0 = __ldcs(&adj4[(size_t)(r0 + 0) * NV + v]);
        int4 a1 = __ldcs(&adj4[(size_t)(r0 + 1) * NV + v]);
        int4 a2 = __ldcs(&adj4[(size_t)(r0 + 2) * NV + v]);
        int4 a3 = __ldcs(&adj4[(size_t)(r0 + 3) * NV + v]);
        float4 p01 = pb4[2 * v];       // {bp0,bn0,bp1,bn1}
        float4 p23 = pb4[2 * v + 1];   // {bp2,bn2,bp3,bn3}

        float q0, q1, q2, q3;
        q0 = fmaxf(p01.x, rho0 * p01.y); q1 = fmaxf(p01.z, rho0 * p01.w);
        q2 = fmaxf(p23.x, rho0 * p23.y); q3 = fmaxf(p23.z, rho0 * p23.w);
        if (a0.x > 0) S0 += q0;
        if (a0.y > 0) S0 += q1;
        if (a0.z > 0) S0 += q2;
        if (a0.w > 0) S0 += q3;
        q0 = fmaxf(p01.x, rho1 * p01.y); q1 = fmaxf(p01.z, rho1 * p01.w);
        q2 = fmaxf(p23.x, rho1 * p23.y); q3 = fmaxf(p23.z, rho1 * p23.w);
        if (a1.x > 0) S1 += q0;
        if (a1.y > 0) S1 += q1;
        if (a1.z > 0) S1 += q2;
        if (a1.w > 0) S1 += q3;
        q0 = fmaxf(p01.x, rho2 * p01.y); q1 = fmaxf(p01.z, rho2 * p01.w);
        q2 = fmaxf(p23.x, rho2 * p23.y); q3 = fmaxf(p23.z, rho2 * p23.w);
        if (a2.x > 0) S2 += q0;
        if (a2.y > 0) S2 += q1;
        if (a2.z > 0) S2 += q2;
        if (a2.w > 0) S2 += q3;
        q0 = fmaxf(p01.x, rho3 * p01.y); q1 = fmaxf(p01.z, rho3 * p01.w);
        q2 = fmaxf(p23.x, rho3 * p23.y); q3 = fmaxf(p23.z, rho3 * p23.w);
        if (a3.x > 0) S3 += q0;
        if (a3.y > 0) S3 += q1;
        if (a3.z > 0) S3 += q2;
        if (a3.w > 0) S3 += q3;

        unsigned n0 = (unsigned)(a0.x | (a0.y << 1) | (a0.z << 2) | (a0.w << 3));
        unsigned n1 = (unsigned)(a1.x | (a1.y << 1) | (a1.z << 2) | (a1.w << 3));
        unsigned n2 = (unsigned)(a2.x | (a2.y << 1) | (a2.z << 2) | (a2.w << 3));
        unsigned n3 = (unsigned)(a3.x | (a3.y << 1) | (a3.z << 2) | (a3.w << 3));
        nr[v] = n0 | (n1 << 8) | (n2 << 16) | (n3 << 24);
    }
    float S[4] = {S0, S1, S2, S3};
#pragma unroll
    for (int r = 0; r < 4; r++) {
        float s = S[r];
#pragma unroll
        for (int o = 16; o; o >>= 1) s += __shfl_xor_sync(0xffffffffu, s, o);
        if ((t & 31) == 0) sred[r][warp] = s;
    }
    __syncthreads();
    if (t < 4) {
        float s = sred[t][0];
#pragma unroll
        for (int w = 1; w < 8; w++) s += sred[t][w];
        float inv = 1.0f / s;
        float2 rw; rw.x = inv; rw.y = srho[t] * inv;
        g_rw[r0 + t] = rw;
    }
}

// ---------------------------------------------------------------------------
// K6: sorted-prefix prune (packed lists) + sparse SpMM (x4) + ELU. Warp/row.
// ---------------------------------------------------------------------------
__global__ void __launch_bounds__(256) k_pruneout(float* __restrict__ out) {
    int t = threadIdx.x;
    int lane = t & 31, w = t >> 5;
    int row = blockIdx.x * 8 + w;
    float2 rw = g_rw[row];
    float py = rw.x, pz = rw.y;
    const unsigned* nib = g_nib4 + (size_t)(row >> 2) * NV;
    int shift = (row & 3) * 8;
    size_t base = (size_t)row * SMAX;
    int cnt = 0;

    int stopU = g_offU[buck(py) + 1];
    for (int k0 = 0; k0 < stopU; k0 += 32) {
        int k = k0 + lane;
        float2 su = g_sU2[k];
        bool cand = (k < stopU) && (su.x < py);
        int j = 0; bool sv = false;
        if (cand) {
            j = __float_as_int(su.y);
            sv = (nib[j >> 2] >> (shift + (j & 3))) & 1u;
        }
        unsigned sb = __ballot_sync(0xffffffffu, sv);
        if (sv) g_sj[base + cnt + __popc(sb & ((1u << lane) - 1u))] = j;
        cnt += __popc(sb);
    }
    int stopV = g_offV[buck(pz) + 1];
    for (int k0 = 0; k0 < stopV; k0 += 32) {
        int k = k0 + lane;
        float4 sv4 = g_sV4[k];
        bool cand = (k < stopV) && (sv4.x < pz) && !(sv4.y < py);
        int j = 0; bool sv = false;
        if (cand) {
            j = __float_as_int(sv4.z);
            sv = (nib[j >> 2] >> (shift + (j & 3))) & 1u;
        }
        unsigned sb = __ballot_sync(0xffffffffu, sv);
        if (sv) g_sj[base + cnt + __popc(sb & ((1u << lane) - 1u))] = j;
        cnt += __popc(sb);
    }

    // ---- SpMM: 4-deep gather pipeline ----
    int n = cnt;
    const int* sj = g_sj + base;
    const float2* whb = reinterpret_cast<const float2*>(g_Wh);
    float ax = 0.f, ay = 0.f, bx = 0.f, by = 0.f;
    int p = 0;
    for (; p + 3 < n; p += 4) {
        int j0 = sj[p], j1 = sj[p + 1], j2 = sj[p + 2], j3 = sj[p + 3];
        float4 t0 = g_jt4[j0], t1 = g_jt4[j1], t2 = g_jt4[j2], t3 = g_jt4[j3];
        float2 a0 = whb[(size_t)j0 * 32 + lane];
        float2 a1 = whb[(size_t)j1 * 32 + lane];
        float2 a2 = whb[(size_t)j2 * 32 + lane];
        float2 a3 = whb[(size_t)j3 * 32 + lane];
        float w0 = fmaxf(fmaxf(py * t0.x, pz * t0.y) - t0.z, 0.f);
        float w1 = fmaxf(fmaxf(py * t1.x, pz * t1.y) - t1.z, 0.f);
        float w2 = fmaxf(fmaxf(py * t2.x, pz * t2.y) - t2.z, 0.f);
        float w3 = fmaxf(fmaxf(py * t3.x, pz * t3.y) - t3.z, 0.f);
        ax = fmaf(w0, a0.x, ax); ay = fmaf(w0, a0.y, ay);
        bx = fmaf(w1, a1.x, bx); by = fmaf(w1, a1.y, by);
        ax = fmaf(w2, a2.x, ax); ay = fmaf(w2, a2.y, ay);
        bx = fmaf(w3, a3.x, bx); by = fmaf(w3, a3.y, by);
    }
    for (; p < n; p++) {
        int j0 = sj[p];
        float4 t0 = g_jt4[j0];
        float2 a0 = whb[(size_t)j0 * 32 + lane];
        float w0 = fmaxf(fmaxf(py * t0.x, pz * t0.y) - t0.z, 0.f);
        ax = fmaf(w0, a0.x, ax); ay = fmaf(w0, a0.y, ay);
    }
    ax += bx; ay += by;
    float2 o;
    o.x = ax > 0.f ? ax : expm1f(ax);
    o.y = ay > 0.f ? ay : expm1f(ay);
    reinterpret_cast<float2*>(out)[(size_t)row * 32 + lane] = o;
}

// ---------------------------------------------------------------------------
extern "C" void kernel_launch(void* const* d_in, const int* in_sizes, int n_in,
                              void* d_out, int out_size) {
    const float* h = nullptr; const float* W = nullptr;
    const float* a_src = nullptr; const float* a_dst = nullptr;
    const float* hub = nullptr; const int* adj = nullptr;
    int a_count = 0;
    for (int i = 0; i < n_in; i++) {
        int s = in_sizes[i];
        if (s == NN * 512)        h = (const float*)d_in[i];
        else if (s == 512 * OUTF) W = (const float*)d_in[i];
        else if (s == OUTF) { if (a_count++ == 0) a_src = (const float*)d_in[i];
                              else                a_dst = (const float*)d_in[i]; }
        else if (s == NN)         hub = (const float*)d_in[i];
        else if (s == NN * NN)    adj = (const int*)d_in[i];
    }

    static cudaStream_t s2 = nullptr;
    static cudaEvent_t evF = nullptr, evJ = nullptr;
    static int inited = 0;
    if (!inited) {
        inited = 1;
        if (cudaStreamCreateWithFlags(&s2, cudaStreamNonBlocking) != cudaSuccess) s2 = nullptr;
        if (s2) {
            if (cudaEventCreateWithFlags(&evF, cudaEventDisableTiming) != cudaSuccess ||
                cudaEventCreateWithFlags(&evJ, cudaEventDisableTiming) != cudaSuccess)
                s2 = nullptr;
        }
    }

    void* p = nullptr;
    cudaGetSymbolAddress(&p, g_histU);
    cudaMemsetAsync(p, 0, NBUCK * sizeof(int));
    cudaGetSymbolAddress(&p, g_histV);
    cudaMemsetAsync(p, 0, NBUCK * sizeof(int));

    k_gemm<<<314, 256>>>(h, W);
    k_edjt<<<1250, 256>>>(a_src, a_dst, hub);

    if (s2) {
        // fork: sort finalize (pref+scatter) runs beside the big adj scan
        cudaEventRecord(evF, 0);
        cudaStreamWaitEvent(s2, evF, 0);
        k_pref<<<1, 1024, 0, s2>>>();
        k_scatter<<<(NN + 255) / 256, 256, 0, s2>>>();
        cudaEventRecord(evJ, s2);
        k_scan<<<2500, 256>>>(adj);
        cudaStreamWaitEvent(0, evJ, 0);
    } else {
        k_pref<<<1, 1024>>>();
        k_scatter<<<(NN + 255) / 256, 256>>>();
        k_scan<<<2500, 256>>>(adj);
    }
    k_pruneout<<<1250, 256>>>((float*)d_out);
}

// round 14
// speedup vs baseline: 1.2977x; 1.1011x over previous
#include <cuda_runtime.h>
#include <math.h>

#define NN 10000
#define NV 2500            // NN/4
#define OUTF 64
#define SMAX 10016
#define NSORT 10048
#define NBUCK 4096

// ---- static scratch ----
__device__ float    g_Wh[NN * OUTF];
__device__ float    g_esrc[NN];
__device__ float    g_qs[512], g_qd[512];   // W @ a_src, W @ a_dst
__device__ float2   g_pb2[NN];        // {bp=e^ed, bn=e^{0.2 ed}} (scan layout)
__device__ float4   g_jt4[NN];        // {bp, bn, hT, 0} (SpMM layout)
__device__ unsigned g_nib4[(size_t)(NN / 4) * NV];
__device__ float2   g_rw[NN];         // {py=1/S'', pz=rho'/S''}
__device__ int      g_sj[(size_t)NN * SMAX];
__device__ float    g_u[NN];
__device__ float2   g_vu[NN];
__device__ int      g_histU[NBUCK], g_histV[NBUCK];
__device__ int      g_offU[NBUCK + 1], g_offV[NBUCK + 1];
__device__ int      g_curU[NBUCK], g_curV[NBUCK];
__device__ float2   g_sU2[NSORT];     // {u, idx_bits}
__device__ float4   g_sV4[NSORT];     // {v, u, idx_bits, 0}

__device__ __forceinline__ unsigned buck(float x) {
    unsigned b = __float_as_uint(x) >> 19;
    return b > (NBUCK - 1u) ? (NBUCK - 1u) : b;
}

// ---------------------------------------------------------------------------
// K0: q_s = W @ a_src, q_d = W @ a_dst (512 dots of length 64)
// ---------------------------------------------------------------------------
__global__ void k_qv(const float* __restrict__ W, const float* __restrict__ a_src,
                     const float* __restrict__ a_dst) {
    int k = blockIdx.x * 256 + threadIdx.x;
    if (k >= 512) return;
    const float4* row = reinterpret_cast<const float4*>(W + (size_t)k * OUTF);
    const float4* as4 = reinterpret_cast<const float4*>(a_src);
    const float4* ad4 = reinterpret_cast<const float4*>(a_dst);
    float s = 0.f, d = 0.f;
#pragma unroll
    for (int c = 0; c < 16; c++) {
        float4 w4 = row[c];
        float4 a4 = as4[c];
        float4 b4 = ad4[c];
        s += w4.x * a4.x + w4.y * a4.y + w4.z * a4.z + w4.w * a4.w;
        d += w4.x * b4.x + w4.y * b4.y + w4.z * b4.z + w4.w * b4.w;
    }
    g_qs[k] = s;
    g_qd[k] = d;
}

// ---------------------------------------------------------------------------
// K1 (side stream): Wh = h @ W. 64 rows x 32 cols per block (314 blocks).
// Needed only by the SpMM in k_pruneout -> overlaps the adj scan.
// ---------------------------------------------------------------------------
__global__ void __launch_bounds__(256) k_gemm(const float* __restrict__ h,
                                              const float* __restrict__ W) {
    __shared__ float h_s[64][33];
    __shared__ float W_s[32][32];
    int tid = threadIdx.x;
    int tx = tid & 15, ty = tid >> 4;
    int rowTile = blockIdx.x >> 1;
    int gc0 = (blockIdx.x & 1) * 32;
    int gr0 = rowTile * 64;
    float acc[4][2];
#pragma unroll
    for (int i = 0; i < 4; i++) { acc[i][0] = 0.f; acc[i][1] = 0.f; }

    for (int k0 = 0; k0 < 512; k0 += 32) {
        __syncthreads();
#pragma unroll
        for (int it = 0; it < 2; it++) {
            int idx = it * 256 + tid;
            int row = idx >> 3, q = idx & 7;
            float4 h4 = make_float4(0.f, 0.f, 0.f, 0.f);
            if (gr0 + row < NN)
                h4 = *reinterpret_cast<const float4*>(h + (size_t)(gr0 + row) * 512 + k0 + q * 4);
            h_s[row][q * 4 + 0] = h4.x; h_s[row][q * 4 + 1] = h4.y;
            h_s[row][q * 4 + 2] = h4.z; h_s[row][q * 4 + 3] = h4.w;
        }
        {
            int kk = tid >> 3, c4 = (tid & 7) * 4;
            float4 w4 = *reinterpret_cast<const float4*>(W + (size_t)(k0 + kk) * OUTF + gc0 + c4);
            *reinterpret_cast<float4*>(&W_s[kk][c4]) = w4;
        }
        __syncthreads();
#pragma unroll
        for (int kk = 0; kk < 32; kk++) {
            float2 wv = *reinterpret_cast<const float2*>(&W_s[kk][tx * 2]);
            float hv0 = h_s[ty * 4 + 0][kk];
            float hv1 = h_s[ty * 4 + 1][kk];
            float hv2 = h_s[ty * 4 + 2][kk];
            float hv3 = h_s[ty * 4 + 3][kk];
            acc[0][0] = fmaf(hv0, wv.x, acc[0][0]); acc[0][1] = fmaf(hv0, wv.y, acc[0][1]);
            acc[1][0] = fmaf(hv1, wv.x, acc[1][0]); acc[1][1] = fmaf(hv1, wv.y, acc[1][1]);
            acc[2][0] = fmaf(hv2, wv.x, acc[2][0]); acc[2][1] = fmaf(hv2, wv.y, acc[2][1]);
            acc[3][0] = fmaf(hv3, wv.x, acc[3][0]); acc[3][1] = fmaf(hv3, wv.y, acc[3][1]);
        }
    }
#pragma unroll
    for (int i = 0; i < 4; i++) {
        int row = gr0 + ty * 4 + i;
        if (row < NN) {
            float2 o; o.x = acc[i][0]; o.y = acc[i][1];
            *reinterpret_cast<float2*>(g_Wh + (size_t)row * OUTF + gc0 + tx * 2) = o;
        }
    }
}

// ---------------------------------------------------------------------------
// K2 (fused): es/ed = h . q  + per-j tables + sort keys + histograms.
// Warp per row reads h directly (no Wh dependency).
// ---------------------------------------------------------------------------
__global__ void k_edjt(const float* __restrict__ h, const float* __restrict__ hub) {
    __shared__ float4 qs_s[128], qd_s[128];
    __shared__ float sed[8];
    int t = threadIdx.x;
    if (t < 128) {
        qs_s[t] = reinterpret_cast<const float4*>(g_qs)[t];
        qd_s[t] = reinterpret_cast<const float4*>(g_qd)[t];
    }
    __syncthreads();
    int lane = t & 31, w = t >> 5;
    int row = blockIdx.x * 8 + w;
    const float4* hrow = reinterpret_cast<const float4*>(h + (size_t)row * 512);
    float s = 0.f, d = 0.f;
#pragma unroll
    for (int i = 0; i < 4; i++) {
        int idx = i * 32 + lane;
        float4 hv = hrow[idx];
        float4 qs = qs_s[idx];
        float4 qd = qd_s[idx];
        s += hv.x * qs.x + hv.y * qs.y + hv.z * qs.z + hv.w * qs.w;
        d += hv.x * qd.x + hv.y * qd.y + hv.z * qd.z + hv.w * qd.w;
    }
#pragma unroll
    for (int o = 16; o; o >>= 1) {
        s += __shfl_xor_sync(0xffffffffu, s, o);
        d += __shfl_xor_sync(0xffffffffu, d, o);
    }
    if (lane == 0) {
        g_esrc[row] = s;
        sed[w] = d;
    }
    __syncthreads();
    if (t < 8) {
        int i = blockIdx.x * 8 + t;
        float ed = sed[t];
        float bp = expf(ed);
        float bn = expf(0.2f * ed);
        float2 pb; pb.x = bp; pb.y = bn;
        g_pb2[i] = pb;
        float hT = hub[i] * 0.01f;
        float4 jt; jt.x = bp; jt.y = bn; jt.z = hT; jt.w = 0.f;
        g_jt4[i] = jt;
        float u = fmaxf((hT / bp) * (1.0f - 2e-6f) - 1e-37f, 0.f);
        float v = fmaxf((hT / bn) * (1.0f - 2e-6f) - 1e-37f, 0.f);
        g_u[i] = u;
        float2 vu; vu.x = v; vu.y = u;
        g_vu[i] = vu;
        atomicAdd(&g_histU[buck(u)], 1);
        atomicAdd(&g_histV[buck(v)], 1);
    }
}

// ---------------------------------------------------------------------------
// K3: exclusive prefix over both histograms — two-level shfl scan
// ---------------------------------------------------------------------------
__global__ void k_pref() {
    __shared__ int wU[32], wV[32];
    int t = threadIdx.x;
    int lane = t & 31, warp = t >> 5;
    int b0 = t * 4;
    int lU[4], lV[4];
    int aU = 0, aV = 0;
#pragma unroll
    for (int q = 0; q < 4; q++) {
        lU[q] = g_histU[b0 + q]; aU += lU[q];
        lV[q] = g_histV[b0 + q]; aV += lV[q];
    }
    int sU = aU, sV = aV;
#pragma unroll
    for (int d = 1; d < 32; d <<= 1) {
        int xU = __shfl_up_sync(0xffffffffu, sU, d);
        int xV = __shfl_up_sync(0xffffffffu, sV, d);
        if (lane >= d) { sU += xU; sV += xV; }
    }
    if (lane == 31) { wU[warp] = sU; wV[warp] = sV; }
    __syncthreads();
    if (warp == 0) {
        int pU = wU[lane], pV = wV[lane];
#pragma unroll
        for (int d = 1; d < 32; d <<= 1) {
            int xU = __shfl_up_sync(0xffffffffu, pU, d);
            int xV = __shfl_up_sync(0xffffffffu, pV, d);
            if (lane >= d) { pU += xU; pV += xV; }
        }
        wU[lane] = pU; wV[lane] = pV;
    }
    __syncthreads();
    int baseU = (warp ? wU[warp - 1] : 0) + sU - aU;
    int baseV = (warp ? wV[warp - 1] : 0) + sV - aV;
#pragma unroll
    for (int q = 0; q < 4; q++) {
        g_offU[b0 + q] = baseU; g_curU[b0 + q] = baseU; baseU += lU[q];
        g_offV[b0 + q] = baseV; g_curV[b0 + q] = baseV; baseV += lV[q];
    }
    if (t == 1023) { g_offU[NBUCK] = baseU; g_offV[NBUCK] = baseV; }
}

// ---------------------------------------------------------------------------
// K4: scatter into bucket-sorted packed arrays
// ---------------------------------------------------------------------------
__global__ void k_scatter() {
    int i = blockIdx.x * 256 + threadIdx.x;
    if (i >= NN) return;
    float u = g_u[i];
    int p1 = atomicAdd(&g_curU[buck(u)], 1);
    float2 e2; e2.x = u; e2.y = __int_as_float(i);
    g_sU2[p1] = e2;
    float2 vu = g_vu[i];
    int p2 = atomicAdd(&g_curV[buck(vu.x)], 1);
    float4 e4; e4.x = vu.x; e4.y = vu.y; e4.z = __int_as_float(i); e4.w = 0.f;
    g_sV4[p2] = e4;
}

// ---------------------------------------------------------------------------
// K5: FUSED adj stream: nibble mask + softmax denominator + row params.
// 4 rows per block (2500 blocks). rho' = exp(-0.8 es).
// ---------------------------------------------------------------------------
__global__ void __launch_bounds__(256) k_scan(const int* __restrict__ adj) {
    __shared__ float srho[4];
    __shared__ float sred[4][8];
    int t = threadIdx.x, warp = t >> 5;
    int b = blockIdx.x;
    int r0 = b * 4;
    if (t < 4) {
        float es = g_esrc[r0 + t];
        srho[t] = expf(-0.8f * es);
    }
    __syncthreads();
    float rho0 = srho[0], rho1 = srho[1], rho2 = srho[2], rho3 = srho[3];
    float S0 = 0.f, S1 = 0.f, S2 = 0.f, S3 = 0.f;

    const int4* adj4 = reinterpret_cast<const int4*>(adj);
    const float4* pb4 = reinterpret_cast<const float4*>(g_pb2);
    unsigned* nr = g_nib4 + (size_t)b * NV;

    for (int v = t; v < NV; v += 256) {
        int4 a0 = __ldcs(&adj4[(size_t)(r0 + 0) * NV + v]);
        int4 a1 = __ldcs(&adj4[(size_t)(r0 + 1) * NV + v]);
        int4 a2 = __ldcs(&adj4[(size_t)(r0 + 2) * NV + v]);
        int4 a3 = __ldcs(&adj4[(size_t)(r0 + 3) * NV + v]);
        float4 p01 = pb4[2 * v];       // {bp0,bn0,bp1,bn1}
        float4 p23 = pb4[2 * v + 1];   // {bp2,bn2,bp3,bn3}

        float q0, q1, q2, q3;
        q0 = fmaxf(p01.x, rho0 * p01.y); q1 = fmaxf(p01.z, rho0 * p01.w);
        q2 = fmaxf(p23.x, rho0 * p23.y); q3 = fmaxf(p23.z, rho0 * p23.w);
        if (a0.x > 0) S0 += q0;
        if (a0.y > 0) S0 += q1;
        if (a0.z > 0) S0 += q2;
        if (a0.w > 0) S0 += q3;
        q0 = fmaxf(p01.x, rho1 * p01.y); q1 = fmaxf(p01.z, rho1 * p01.w);
        q2 = fmaxf(p23.x, rho1 * p23.y); q3 = fmaxf(p23.z, rho1 * p23.w);
        if (a1.x > 0) S1 += q0;
        if (a1.y > 0) S1 += q1;
        if (a1.z > 0) S1 += q2;
        if (a1.w > 0) S1 += q3;
        q0 = fmaxf(p01.x, rho2 * p01.y); q1 = fmaxf(p01.z, rho2 * p01.w);
        q2 = fmaxf(p23.x, rho2 * p23.y); q3 = fmaxf(p23.z, rho2 * p23.w);
        if (a2.x > 0) S2 += q0;
        if (a2.y > 0) S2 += q1;
        if (a2.z > 0) S2 += q2;
        if (a2.w > 0) S2 += q3;
        q0 = fmaxf(p01.x, rho3 * p01.y); q1 = fmaxf(p01.z, rho3 * p01.w);
        q2 = fmaxf(p23.x, rho3 * p23.y); q3 = fmaxf(p23.z, rho3 * p23.w);
        if (a3.x > 0) S3 += q0;
        if (a3.y > 0) S3 += q1;
        if (a3.z > 0) S3 += q2;
        if (a3.w > 0) S3 += q3;

        unsigned n0 = (unsigned)(a0.x | (a0.y << 1) | (a0.z << 2) | (a0.w << 3));
        unsigned n1 = (unsigned)(a1.x | (a1.y << 1) | (a1.z << 2) | (a1.w << 3));
        unsigned n2 = (unsigned)(a2.x | (a2.y << 1) | (a2.z << 2) | (a2.w << 3));
        unsigned n3 = (unsigned)(a3.x | (a3.y << 1) | (a3.z << 2) | (a3.w << 3));
        nr[v] = n0 | (n1 << 8) | (n2 << 16) | (n3 << 24);
    }
    float S[4] = {S0, S1, S2, S3};
#pragma unroll
    for (int r = 0; r < 4; r++) {
        float s = S[r];
#pragma unroll
        for (int o = 16; o; o >>= 1) s += __shfl_xor_sync(0xffffffffu, s, o);
        if ((t & 31) == 0) sred[r][warp] = s;
    }
    __syncthreads();
    if (t < 4) {
        float s = sred[t][0];
#pragma unroll
        for (int w = 1; w < 8; w++) s += sred[t][w];
        float inv = 1.0f / s;
        float2 rw; rw.x = inv; rw.y = srho[t] * inv;
        g_rw[r0 + t] = rw;
    }
}

// ---------------------------------------------------------------------------
// K6: sorted-prefix prune (packed lists) + sparse SpMM (x4) + ELU. Warp/row.
// ---------------------------------------------------------------------------
__global__ void __launch_bounds__(256) k_pruneout(float* __restrict__ out) {
    int t = threadIdx.x;
    int lane = t & 31, w = t >> 5;
    int row = blockIdx.x * 8 + w;
    float2 rw = g_rw[row];
    float py = rw.x, pz = rw.y;
    const unsigned* nib = g_nib4 + (size_t)(row >> 2) * NV;
    int shift = (row & 3) * 8;
    size_t base = (size_t)row * SMAX;
    int cnt = 0;

    int stopU = g_offU[buck(py) + 1];
    for (int k0 = 0; k0 < stopU; k0 += 32) {
        int k = k0 + lane;
        float2 su = g_sU2[k];
        bool cand = (k < stopU) && (su.x < py);
        int j = 0; bool sv = false;
        if (cand) {
            j = __float_as_int(su.y);
            sv = (nib[j >> 2] >> (shift + (j & 3))) & 1u;
        }
        unsigned sb = __ballot_sync(0xffffffffu, sv);
        if (sv) g_sj[base + cnt + __popc(sb & ((1u << lane) - 1u))] = j;
        cnt += __popc(sb);
    }
    int stopV = g_offV[buck(pz) + 1];
    for (int k0 = 0; k0 < stopV; k0 += 32) {
        int k = k0 + lane;
        float4 sv4 = g_sV4[k];
        bool cand = (k < stopV) && (sv4.x < pz) && !(sv4.y < py);
        int j = 0; bool sv = false;
        if (cand) {
            j = __float_as_int(sv4.z);
            sv = (nib[j >> 2] >> (shift + (j & 3))) & 1u;
        }
        unsigned sb = __ballot_sync(0xffffffffu, sv);
        if (sv) g_sj[base + cnt + __popc(sb & ((1u << lane) - 1u))] = j;
        cnt += __popc(sb);
    }

    // ---- SpMM: 4-deep gather pipeline ----
    int n = cnt;
    const int* sj = g_sj + base;
    const float2* whb = reinterpret_cast<const float2*>(g_Wh);
    float ax = 0.f, ay = 0.f, bx = 0.f, by = 0.f;
    int p = 0;
    for (; p + 3 < n; p += 4) {
        int j0 = sj[p], j1 = sj[p + 1], j2 = sj[p + 2], j3 = sj[p + 3];
        float4 t0 = g_jt4[j0], t1 = g_jt4[j1], t2 = g_jt4[j2], t3 = g_jt4[j3];
        float2 a0 = whb[(size_t)j0 * 32 + lane];
        float2 a1 = whb[(size_t)j1 * 32 + lane];
        float2 a2 = whb[(size_t)j2 * 32 + lane];
        float2 a3 = whb[(size_t)j3 * 32 + lane];
        float w0 = fmaxf(fmaxf(py * t0.x, pz * t0.y) - t0.z, 0.f);
        float w1 = fmaxf(fmaxf(py * t1.x, pz * t1.y) - t1.z, 0.f);
        float w2 = fmaxf(fmaxf(py * t2.x, pz * t2.y) - t2.z, 0.f);
        float w3 = fmaxf(fmaxf(py * t3.x, pz * t3.y) - t3.z, 0.f);
        ax = fmaf(w0, a0.x, ax); ay = fmaf(w0, a0.y, ay);
        bx = fmaf(w1, a1.x, bx); by = fmaf(w1, a1.y, by);
        ax = fmaf(w2, a2.x, ax); ay = fmaf(w2, a2.y, ay);
        bx = fmaf(w3, a3.x, bx); by = fmaf(w3, a3.y, by);
    }
    for (; p < n; p++) {
        int j0 = sj[p];
        float4 t0 = g_jt4[j0];
        float2 a0 = whb[(size_t)j0 * 32 + lane];
        float w0 = fmaxf(fmaxf(py * t0.x, pz * t0.y) - t0.z, 0.f);
        ax = fmaf(w0, a0.x, ax); ay = fmaf(w0, a0.y, ay);
    }
    ax += bx; ay += by;
    float2 o;
    o.x = ax > 0.f ? ax : expm1f(ax);
    o.y = ay > 0.f ? ay : expm1f(ay);
    reinterpret_cast<float2*>(out)[(size_t)row * 32 + lane] = o;
}

// ---------------------------------------------------------------------------
extern "C" void kernel_launch(void* const* d_in, const int* in_sizes, int n_in,
                              void* d_out, int out_size) {
    const float* h = nullptr; const float* W = nullptr;
    const float* a_src = nullptr; const float* a_dst = nullptr;
    const float* hub = nullptr; const int* adj = nullptr;
    int a_count = 0;
    for (int i = 0; i < n_in; i++) {
        int s = in_sizes[i];
        if (s == NN * 512)        h = (const float*)d_in[i];
        else if (s == 512 * OUTF) W = (const float*)d_in[i];
        else if (s == OUTF) { if (a_count++ == 0) a_src = (const float*)d_in[i];
                              else                a_dst = (const float*)d_in[i]; }
        else if (s == NN)         hub = (const float*)d_in[i];
        else if (s == NN * NN)    adj = (const int*)d_in[i];
    }

    static cudaStream_t s2 = nullptr, s3 = nullptr;
    static cudaEvent_t evF = nullptr, evJ = nullptr, evG = nullptr, evF3 = nullptr;
    static int inited = 0;
    if (!inited) {
        inited = 1;
        bool ok = cudaStreamCreateWithFlags(&s2, cudaStreamNonBlocking) == cudaSuccess &&
                  cudaStreamCreateWithFlags(&s3, cudaStreamNonBlocking) == cudaSuccess &&
                  cudaEventCreateWithFlags(&evF, cudaEventDisableTiming) == cudaSuccess &&
                  cudaEventCreateWithFlags(&evJ, cudaEventDisableTiming) == cudaSuccess &&
                  cudaEventCreateWithFlags(&evG, cudaEventDisableTiming) == cudaSuccess &&
                  cudaEventCreateWithFlags(&evF3, cudaEventDisableTiming) == cudaSuccess;
        if (!ok) { s2 = nullptr; s3 = nullptr; }
    }

    void* p = nullptr;
    cudaGetSymbolAddress(&p, g_histU);
    cudaMemsetAsync(p, 0, NBUCK * sizeof(int));
    cudaGetSymbolAddress(&p, g_histV);
    cudaMemsetAsync(p, 0, NBUCK * sizeof(int));

    if (s2) {
        // side stream s3: Wh GEMM (only pruneout needs it) overlaps everything
        cudaEventRecord(evF3, 0);
        cudaStreamWaitEvent(s3, evF3, 0);
        k_gemm<<<314, 256, 0, s3>>>(h, W);
        cudaEventRecord(evG, s3);

        k_qv<<<2, 256>>>(W, a_src, a_dst);
        k_edjt<<<1250, 256>>>(h, hub);

        // side stream s2: sort finalize beside the adj scan
        cudaEventRecord(evF, 0);
        cudaStreamWaitEvent(s2, evF, 0);
        k_pref<<<1, 1024, 0, s2>>>();
        k_scatter<<<(NN + 255) / 256, 256, 0, s2>>>();
        cudaEventRecord(evJ, s2);

        k_scan<<<2500, 256>>>(adj);
        cudaStreamWaitEvent(0, evJ, 0);
        cudaStreamWaitEvent(0, evG, 0);
    } else {
        k_gemm<<<314, 256>>>(h, W);
        k_qv<<<2, 256>>>(W, a_src, a_dst);
        k_edjt<<<1250, 256>>>(h, hub);
        k_pref<<<1, 1024>>>();
        k_scatter<<<(NN + 255) / 256, 256>>>();
        k_scan<<<2500, 256>>>(adj);
    }
    k_pruneout<<<1250, 256>>>((float*)d_out);
}